// round 1
// baseline (speedup 1.0000x reference)
#include <cuda_runtime.h>
#include <cuda_fp16.h>
#include <cstdint>

#define D_MODEL 1024
#define BB 2
#define SS 2048
#define NTOK (BB*SS)
#define V1N 200
#define V2N 160
#define NL 8
#define TC 32
#define NC (SS/TC)   /* 64 */
#define EPS 1e-6f

// ---------------- scratch (static device allocations are allowed) ----------
__device__ float g_x[NTOK * D_MODEL];          // model state, 16.7 MB (L2 resident)
__device__ float g_invr[NTOK];                 // rmsnorm scale for next consumer
__device__ float g_hfin[BB * NC * D_MODEL];    // chunk-final h (phase A)
__device__ float g_hcar[BB * NC * D_MODEL];    // h entering each chunk (phase B)

// ---------------- helpers ---------------------------------------------------
__device__ __forceinline__ float warp_sum(float v){
#pragma unroll
    for (int o = 16; o; o >>= 1) v += __shfl_xor_sync(0xffffffffu, v, o);
    return v;
}
__device__ __forceinline__ float sigmoidf_(float x){ return 1.f / (1.f + expf(-x)); }
__device__ __forceinline__ float geluf_(float x){
    float x3 = x * x * x;
    return 0.5f * x * (1.f + tanhf(0.7978845608028654f * (x + 0.044715f * x3)));
}

__device__ __forceinline__ void mma16816(float& d0, float& d1, float& d2, float& d3,
                                         uint32_t a0, uint32_t a1, uint32_t a2, uint32_t a3,
                                         uint32_t b0, uint32_t b1){
    asm volatile(
        "mma.sync.aligned.m16n8k16.row.col.f32.f16.f16.f32 "
        "{%0,%1,%2,%3},{%4,%5,%6,%7},{%8,%9},{%0,%1,%2,%3};\n"
        : "+f"(d0), "+f"(d1), "+f"(d2), "+f"(d3)
        : "r"(a0), "r"(a1), "r"(a2), "r"(a3), "r"(b0), "r"(b1));
}

// ---------------- embed: x = outer(core1[i1], core2[i2]); invr for layer0 ---
__global__ void k_embed(const int* __restrict__ ids, const float* __restrict__ c1,
                        const float* __restrict__ c2){
    int tok  = blockIdx.x * 8 + (threadIdx.x >> 5);
    int lane = threadIdx.x & 31;
    int id = ids[tok];
    int i1 = id / V2N, i2 = id % V2N;
    const float* r1 = c1 + i1 * 32;
    const float* r2 = c2 + i2 * 32;
    float* xp = g_x + (size_t)tok * D_MODEL;
    float ss = 0.f;
#pragma unroll
    for (int k = 0; k < 8; k++){
        int e = k * 128 + lane * 4;           // 4 consecutive elems, same i, j..j+3
        int i = e >> 5, j = e & 31;
        float a = r1[i];
        float4 b = *(const float4*)(r2 + j);
        float4 v; v.x = a*b.x; v.y = a*b.y; v.z = a*b.z; v.w = a*b.w;
        *(float4*)(xp + e) = v;
        ss += v.x*v.x + v.y*v.y + v.z*v.z + v.w*v.w;
    }
    ss = warp_sum(ss);
    if (lane == 0) g_invr[tok] = rsqrtf(ss * (1.f/1024.f) + EPS);
}

// ---------------- scan phase A: local chunk scans (h_in = 0) ---------------
__global__ void k_scanA(const float* __restrict__ lam, const float* __restrict__ vv,
                        const float* __restrict__ n1w, int l){
    int bid = blockIdx.x;
    int grp = bid & 3;
    int ch  = (bid >> 2) & (NC - 1);
    int b   = bid >> 8;                       // NC*4 = 256
    int c   = grp * 256 + threadIdx.x;
    int off = l * D_MODEL + c;
    float a  = sigmoidf_(lam[off]);
    float vn = vv[off] * n1w[off];
    __shared__ float ir[TC];
    if (threadIdx.x < TC) ir[threadIdx.x] = g_invr[b * SS + ch * TC + threadIdx.x];
    __syncthreads();
    const float* xp = g_x + ((size_t)(b * SS + ch * TC)) * D_MODEL + c;
    float h = 0.f;
#pragma unroll
    for (int t = 0; t < TC; t++)
        h = fmaf(a, h, (vn * ir[t]) * xp[t * D_MODEL]);
    g_hfin[(b * NC + ch) * D_MODEL + c] = h;
}

// ---------------- scan phase B: cross-chunk serial scan --------------------
__global__ void k_scanB(const float* __restrict__ lam, int l){
    int b = blockIdx.x, c = threadIdx.x;
    float a = sigmoidf_(lam[l * D_MODEL + c]);
    float aT = a * a; aT *= aT; aT *= aT; aT *= aT; aT *= aT;   // a^32
    float h = 0.f;
#pragma unroll 4
    for (int k = 0; k < NC; k++){
        g_hcar[(b * NC + k) * D_MODEL + c] = h;
        h = fmaf(aT, h, g_hfin[(b * NC + k) * D_MODEL + c]);
    }
}

// ---------------- scan phase C: recompute with h_in; x += u*h --------------
__global__ void k_scanC(const float* __restrict__ lam, const float* __restrict__ vv,
                        const float* __restrict__ uu, const float* __restrict__ n1w, int l){
    int bid = blockIdx.x;
    int grp = bid & 3;
    int ch  = (bid >> 2) & (NC - 1);
    int b   = bid >> 8;
    int c   = grp * 256 + threadIdx.x;
    int off = l * D_MODEL + c;
    float a  = sigmoidf_(lam[off]);
    float vn = vv[off] * n1w[off];
    float un = uu[off];
    __shared__ float ir[TC];
    if (threadIdx.x < TC) ir[threadIdx.x] = g_invr[b * SS + ch * TC + threadIdx.x];
    __syncthreads();
    float* xp = g_x + ((size_t)(b * SS + ch * TC)) * D_MODEL + c;
    float h = g_hcar[(b * NC + ch) * D_MODEL + c];
#pragma unroll
    for (int t = 0; t < TC; t++){
        float xv = xp[t * D_MODEL];
        h = fmaf(a, h, (vn * ir[t]) * xv);
        xp[t * D_MODEL] = fmaf(un, h, xv);
    }
}

// ---------------- FFN: rmsnorm2 + rank-2 FFN + residual; next invr ---------
__global__ void k_ffn(const float* __restrict__ w1, const float* __restrict__ w2,
                      const float* __restrict__ n2w, int l){
    int tok  = blockIdx.x * 8 + (threadIdx.x >> 5);
    int lane = threadIdx.x & 31;
    float* xp = g_x + (size_t)tok * D_MODEL;
    float xv[32];
    float ss = 0.f;
#pragma unroll
    for (int k = 0; k < 8; k++){
        float4 t = *(const float4*)(xp + k * 128 + lane * 4);
        xv[4*k+0]=t.x; xv[4*k+1]=t.y; xv[4*k+2]=t.z; xv[4*k+3]=t.w;
        ss += t.x*t.x + t.y*t.y + t.z*t.z + t.w*t.w;
    }
    ss = warp_sum(ss);
    float invr = rsqrtf(ss * (1.f/1024.f) + EPS);
    const float* n2  = n2w + l * D_MODEL;
    const float2* w1p = (const float2*)(w1 + (size_t)l * D_MODEL * 2);
    float d0 = 0.f, d1 = 0.f;
#pragma unroll
    for (int k = 0; k < 8; k++){
        int e = k * 128 + lane * 4;
        float4 nw = *(const float4*)(n2 + e);
#pragma unroll
        for (int r = 0; r < 4; r++){
            float h = xv[4*k+r] * invr * ((const float*)&nw)[r];
            float2 w = w1p[e + r];
            d0 = fmaf(h, w.x, d0);
            d1 = fmaf(h, w.y, d1);
        }
    }
    d0 = warp_sum(d0);
    d1 = warp_sum(d1);
    float g0 = geluf_(d0), g1 = geluf_(d1);
    const float* w2a = w2 + (size_t)l * 2 * D_MODEL;
    const float* w2b = w2a + D_MODEL;
    float ss2 = 0.f;
#pragma unroll
    for (int k = 0; k < 8; k++){
        int e = k * 128 + lane * 4;
        float4 wa = *(const float4*)(w2a + e);
        float4 wb = *(const float4*)(w2b + e);
        float4 o;
        o.x = xv[4*k+0] + g0*wa.x + g1*wb.x;
        o.y = xv[4*k+1] + g0*wa.y + g1*wb.y;
        o.z = xv[4*k+2] + g0*wa.z + g1*wb.z;
        o.w = xv[4*k+3] + g0*wa.w + g1*wb.w;
        *(float4*)(xp + e) = o;
        ss2 += o.x*o.x + o.y*o.y + o.z*o.z + o.w*o.w;
    }
    ss2 = warp_sum(ss2);
    if (lane == 0) g_invr[tok] = rsqrtf(ss2 * (1.f/1024.f) + EPS);
}

// ---------------- logits: TT-factored, fp16 HMMA, one token per CTA --------
// Yt[v2,i] = sum_j core2[v2,j] * xn[i*32+j]   (M=160,N=32,K=32)
// out[v1,v2] = sum_i core1[v1,i] * Yt[v2,i]   (M=208(pad),N=160,K=32)
#define PITCH 40   /* half pitch: 80B row stride -> conflict-free frag loads */
__global__ __launch_bounds__(256) void k_logits(const float* __restrict__ c1,
                                                const float* __restrict__ c2,
                                                const float* __restrict__ fw,
                                                float* __restrict__ out){
    __shared__ half s_x [32  * PITCH];
    __shared__ half s_c2[160 * PITCH];
    __shared__ half s_c1[208 * PITCH];
    __shared__ half s_Yt[160 * PITCH];
    int tok = blockIdx.x;
    int tid = threadIdx.x;
    const float* xp = g_x + (size_t)tok * D_MODEL;
    float invr = g_invr[tok];
    for (int e = tid; e < 1024; e += 256)
        s_x[(e >> 5) * PITCH + (e & 31)] = __float2half_rn(xp[e] * invr * fw[e]);
    for (int e = tid; e < 160 * 32; e += 256)
        s_c2[(e >> 5) * PITCH + (e & 31)] = __float2half_rn(c2[e]);
    for (int e = tid; e < 208 * 32; e += 256){
        int v1 = e >> 5;
        s_c1[v1 * PITCH + (e & 31)] = __float2half_rn(v1 < V1N ? c1[e] : 0.f);
    }
    __syncthreads();

    int w = tid >> 5, lane = tid & 31, g = lane >> 2, tg = lane & 3;

    // stage 1: 10 (v2-tiles) x 4 (i-tiles)
    for (int id = w; id < 40; id += 8){
        int mt = id >> 2, nt = id & 3;
        float a0c = 0.f, a1c = 0.f, a2c = 0.f, a3c = 0.f;
#pragma unroll
        for (int ks = 0; ks < 2; ks++){
            int ac = ks * 16 + 2 * tg;
            uint32_t A0 = *(const uint32_t*)(s_c2 + (mt*16 + g    ) * PITCH + ac);
            uint32_t A1 = *(const uint32_t*)(s_c2 + (mt*16 + g + 8) * PITCH + ac);
            uint32_t A2 = *(const uint32_t*)(s_c2 + (mt*16 + g    ) * PITCH + ac + 8);
            uint32_t A3 = *(const uint32_t*)(s_c2 + (mt*16 + g + 8) * PITCH + ac + 8);
            uint32_t B0 = *(const uint32_t*)(s_x  + (nt*8  + g    ) * PITCH + ac);
            uint32_t B1 = *(const uint32_t*)(s_x  + (nt*8  + g    ) * PITCH + ac + 8);
            mma16816(a0c, a1c, a2c, a3c, A0, A1, A2, A3, B0, B1);
        }
        int col = nt * 8 + 2 * tg;
        *(half2*)(s_Yt + (mt*16 + g    ) * PITCH + col) = __floats2half2_rn(a0c, a1c);
        *(half2*)(s_Yt + (mt*16 + g + 8) * PITCH + col) = __floats2half2_rn(a2c, a3c);
    }
    __syncthreads();

    // stage 2: 13 (v1-tiles, padded to 208) x 20 (v2-tiles)
    float* op = out + (size_t)tok * (V1N * V2N);
    for (int id = w; id < 260; id += 8){
        int mt = id / 20, nt = id % 20;
        float a0c = 0.f, a1c = 0.f, a2c = 0.f, a3c = 0.f;
#pragma unroll
        for (int ks = 0; ks < 2; ks++){
            int ac = ks * 16 + 2 * tg;
            uint32_t A0 = *(const uint32_t*)(s_c1 + (mt*16 + g    ) * PITCH + ac);
            uint32_t A1 = *(const uint32_t*)(s_c1 + (mt*16 + g + 8) * PITCH + ac);
            uint32_t A2 = *(const uint32_t*)(s_c1 + (mt*16 + g    ) * PITCH + ac + 8);
            uint32_t A3 = *(const uint32_t*)(s_c1 + (mt*16 + g + 8) * PITCH + ac + 8);
            uint32_t B0 = *(const uint32_t*)(s_Yt + (nt*8  + g    ) * PITCH + ac);
            uint32_t B1 = *(const uint32_t*)(s_Yt + (nt*8  + g    ) * PITCH + ac + 8);
            mma16816(a0c, a1c, a2c, a3c, A0, A1, A2, A3, B0, B1);
        }
        int r0 = mt * 16 + g, r1 = r0 + 8, col = nt * 8 + 2 * tg;
        if (r0 < V1N) *(float2*)(op + r0 * V2N + col) = make_float2(a0c, a1c);
        if (r1 < V1N) *(float2*)(op + r1 * V2N + col) = make_float2(a2c, a3c);
    }
}

// ---------------- launch ----------------------------------------------------
extern "C" void kernel_launch(void* const* d_in, const int* in_sizes, int n_in,
                              void* d_out, int out_size){
    const int*   ids = (const int*)  d_in[0];
    const float* c1  = (const float*)d_in[1];
    const float* c2  = (const float*)d_in[2];
    const float* lam = (const float*)d_in[3];
    const float* u   = (const float*)d_in[4];
    const float* v   = (const float*)d_in[5];
    const float* w1  = (const float*)d_in[6];
    const float* w2  = (const float*)d_in[7];
    const float* n1w = (const float*)d_in[8];
    const float* n2w = (const float*)d_in[9];
    const float* fw  = (const float*)d_in[10];
    float* out = (float*)d_out;

    k_embed<<<NTOK/8, 256>>>(ids, c1, c2);
    for (int l = 0; l < NL; l++){
        k_scanA<<<BB*NC*4, 256>>>(lam, v, n1w, l);
        k_scanB<<<BB, 1024>>>(lam, l);
        k_scanC<<<BB*NC*4, 256>>>(lam, v, u, n1w, l);
        k_ffn  <<<NTOK/8, 256>>>(w1, w2, n2w, l);
    }
    k_logits<<<NTOK, 256>>>(c1, c2, fw, out);
}

// round 2
// speedup vs baseline: 1.5141x; 1.5141x over previous
#include <cuda_runtime.h>
#include <cuda_fp16.h>
#include <cstdint>

#define D_MODEL 1024
#define BB 2
#define SS 2048
#define NTOK (BB*SS)
#define V1N 200
#define V2N 160
#define NL 8
#define TC 32
#define NC (SS/TC)   /* 64 */
#define EPS 1e-6f

// ---------------- scratch -----------------------------------------------
__device__ float g_x[NTOK * D_MODEL];          // model state (16.7 MB, L2-resident)
__device__ float g_invr[NTOK];                 // rmsnorm scale for next consumer
__device__ float g_hfin[2][BB * NC * D_MODEL]; // chunk-local scan results (ping-pong)

// ---------------- helpers ------------------------------------------------
__device__ __forceinline__ float warp_sum(float v){
#pragma unroll
    for (int o = 16; o; o >>= 1) v += __shfl_xor_sync(0xffffffffu, v, o);
    return v;
}
__device__ __forceinline__ float sigmoidf_(float x){ return 1.f / (1.f + expf(-x)); }
__device__ __forceinline__ float geluf_(float x){
    float x3 = x * x * x;
    return 0.5f * x * (1.f + tanhf(0.7978845608028654f * (x + 0.044715f * x3)));
}
__device__ __forceinline__ void mma16816(float& d0, float& d1, float& d2, float& d3,
                                         uint32_t a0, uint32_t a1, uint32_t a2, uint32_t a3,
                                         uint32_t b0, uint32_t b1){
    asm volatile(
        "mma.sync.aligned.m16n8k16.row.col.f32.f16.f16.f32 "
        "{%0,%1,%2,%3},{%4,%5,%6,%7},{%8,%9},{%0,%1,%2,%3};\n"
        : "+f"(d0), "+f"(d1), "+f"(d2), "+f"(d3)
        : "r"(a0), "r"(a1), "r"(a2), "r"(a3), "r"(b0), "r"(b1));
}

// =========================================================================
// embed: block = one chunk (32 tokens x 1024 ch). Computes embedding, invr,
// writes x, and phase-A (chunk-local scan) for layer 0 into g_hfin[0].
// =========================================================================
__global__ __launch_bounds__(1024, 1) void k_embed(
    const int* __restrict__ ids, const float* __restrict__ c1,
    const float* __restrict__ c2, const float* __restrict__ lam,
    const float* __restrict__ vv, const float* __restrict__ n1w)
{
    extern __shared__ float sx[];              // TC * D_MODEL
    __shared__ float s_ir[TC];
    int b  = blockIdx.x >> 6;
    int ch = blockIdx.x & (NC - 1);
    int c  = threadIdx.x;
    int t  = c >> 5, lane = c & 31;
    int tok = b * SS + ch * TC + t;

    int id = ids[tok];
    int i1 = id / V2N, i2 = id % V2N;
    const float* r1 = c1 + i1 * 32;
    const float* r2 = c2 + i2 * 32;
    float* xw = g_x + (size_t)tok * D_MODEL;
    float* xr = sx + t * D_MODEL;
    float ss = 0.f;
#pragma unroll
    for (int k = 0; k < 8; k++){
        int e = k * 128 + lane * 4;
        int i = e >> 5, j = e & 31;
        float a = r1[i];
        float4 bq = *(const float4*)(r2 + j);
        float4 v4; v4.x = a*bq.x; v4.y = a*bq.y; v4.z = a*bq.z; v4.w = a*bq.w;
        *(float4*)(xr + e) = v4;
        *(float4*)(xw + e) = v4;
        ss += v4.x*v4.x + v4.y*v4.y + v4.z*v4.z + v4.w*v4.w;
    }
    ss = warp_sum(ss);
    if (lane == 0){
        float r = rsqrtf(ss * (1.f/1024.f) + EPS);
        s_ir[t] = r;
        g_invr[tok] = r;
    }
    __syncthreads();

    // phase A for layer 0
    float a0  = sigmoidf_(lam[c]);
    float vn0 = vv[c] * n1w[c];
    float h = 0.f;
#pragma unroll
    for (int tt = 0; tt < TC; tt++)
        h = fmaf(a0, h, (vn0 * s_ir[tt]) * sx[tt * D_MODEL + c]);
    g_hfin[0][(b * NC + ch) * D_MODEL + c] = h;
}

// =========================================================================
// fused layer: carry (Horner over earlier chunks' hfin) + scan + x update +
// FFN + new invr + phase A for next layer. One block per chunk, single wave.
// =========================================================================
__global__ __launch_bounds__(1024, 1) void k_layer(
    const float* __restrict__ lam, const float* __restrict__ uu,
    const float* __restrict__ vv, const float* __restrict__ w1,
    const float* __restrict__ w2, const float* __restrict__ n1w,
    const float* __restrict__ n2w, int l)
{
    extern __shared__ float sx[];              // TC * D_MODEL
    __shared__ float s_n2w[D_MODEL];
    __shared__ float s_w1x[D_MODEL];
    __shared__ float s_w1y[D_MODEL];
    __shared__ float s_w2a[D_MODEL];
    __shared__ float s_w2b[D_MODEL];
    __shared__ float s_ir[TC], s_ir2[TC];

    int b  = blockIdx.x >> 6;
    int ch = blockIdx.x & (NC - 1);
    int c  = threadIdx.x;

    // stage FFN weights
    s_n2w[c] = n2w[l * D_MODEL + c];
    float2 w1p = ((const float2*)(w1 + (size_t)l * D_MODEL * 2))[c];
    s_w1x[c] = w1p.x;  s_w1y[c] = w1p.y;
    s_w2a[c] = w2[(size_t)l * 2 * D_MODEL + c];
    s_w2b[c] = w2[(size_t)l * 2 * D_MODEL + D_MODEL + c];
    if (c < TC) s_ir[c] = g_invr[b * SS + ch * TC + c];

    int off = l * D_MODEL + c;
    float a  = sigmoidf_(lam[off]);
    float vn = vv[off] * n1w[off];
    float un = uu[off];
    float aT = a * a; aT *= aT; aT *= aT; aT *= aT; aT *= aT;   // a^32

    // carry from earlier chunks (Horner over this layer's hfin)
    const float* hf = g_hfin[l & 1] + (size_t)b * NC * D_MODEL + c;
    float carry = 0.f;
#pragma unroll 8
    for (int k = 0; k < ch; k++)
        carry = fmaf(aT, carry, hf[(size_t)k * D_MODEL]);

    // load x chunk into smem (coalesced float4)
    const float4* xg4 = (const float4*)(g_x + ((size_t)(b * SS + ch * TC)) * D_MODEL);
    float4* sx4 = (float4*)sx;
#pragma unroll
    for (int k = 0; k < 8; k++) sx4[k * 1024 + c] = xg4[k * 1024 + c];
    __syncthreads();

    // scan + residual (per channel, from smem)
    float h = carry;
#pragma unroll
    for (int t = 0; t < TC; t++){
        float xv = sx[t * D_MODEL + c];
        h = fmaf(a, h, (vn * s_ir[t]) * xv);
        sx[t * D_MODEL + c] = fmaf(un, h, xv);
    }
    __syncthreads();

    // FFN: warp per token, data from smem
    int t = c >> 5, lane = c & 31;
    float* xr = sx + t * D_MODEL;
    float ss = 0.f;
#pragma unroll
    for (int k = 0; k < 8; k++){
        float4 q = *(const float4*)(xr + k * 128 + lane * 4);
        ss += q.x*q.x + q.y*q.y + q.z*q.z + q.w*q.w;
    }
    ss = warp_sum(ss);
    float invr = rsqrtf(ss * (1.f/1024.f) + EPS);

    float d0 = 0.f, d1 = 0.f;
#pragma unroll
    for (int k = 0; k < 8; k++){
        int e = k * 128 + lane * 4;
        float4 q  = *(const float4*)(xr + e);
        float4 nw = *(const float4*)(s_n2w + e);
        float4 wx = *(const float4*)(s_w1x + e);
        float4 wy = *(const float4*)(s_w1y + e);
#pragma unroll
        for (int r = 0; r < 4; r++){
            float hh = ((const float*)&q)[r] * invr * ((const float*)&nw)[r];
            d0 = fmaf(hh, ((const float*)&wx)[r], d0);
            d1 = fmaf(hh, ((const float*)&wy)[r], d1);
        }
    }
    d0 = warp_sum(d0);
    d1 = warp_sum(d1);
    float g0 = geluf_(d0), g1 = geluf_(d1);

    float* xw = g_x + (size_t)(b * SS + ch * TC + t) * D_MODEL;
    float ss2 = 0.f;
#pragma unroll
    for (int k = 0; k < 8; k++){
        int e = k * 128 + lane * 4;
        float4 q  = *(const float4*)(xr + e);
        float4 wa = *(const float4*)(s_w2a + e);
        float4 wb = *(const float4*)(s_w2b + e);
        float4 o;
        o.x = q.x + g0*wa.x + g1*wb.x;
        o.y = q.y + g0*wa.y + g1*wb.y;
        o.z = q.z + g0*wa.z + g1*wb.z;
        o.w = q.w + g0*wa.w + g1*wb.w;
        *(float4*)(xr + e) = o;
        *(float4*)(xw + e) = o;
        ss2 += o.x*o.x + o.y*o.y + o.z*o.z + o.w*o.w;
    }
    ss2 = warp_sum(ss2);
    if (lane == 0){
        float r2 = rsqrtf(ss2 * (1.f/1024.f) + EPS);
        s_ir2[t] = r2;
        g_invr[b * SS + ch * TC + t] = r2;
    }
    __syncthreads();

    // phase A for next layer (chunk-local scan with next layer's params)
    if (l < NL - 1){
        int off2 = (l + 1) * D_MODEL + c;
        float a2  = sigmoidf_(lam[off2]);
        float vn2 = vv[off2] * n1w[off2];
        float h2 = 0.f;
#pragma unroll
        for (int tt = 0; tt < TC; tt++)
            h2 = fmaf(a2, h2, (vn2 * s_ir2[tt]) * sx[tt * D_MODEL + c]);
        g_hfin[(l + 1) & 1][(b * NC + ch) * D_MODEL + c] = h2;
    }
}

// =========================================================================
// logits: TT-factored, fp16 HMMA, one token per CTA (store-bound, ~524MB)
// =========================================================================
#define PITCH 40
__global__ __launch_bounds__(256) void k_logits(const float* __restrict__ c1,
                                                const float* __restrict__ c2,
                                                const float* __restrict__ fw,
                                                float* __restrict__ out){
    __shared__ half s_x [32  * PITCH];
    __shared__ half s_c2[160 * PITCH];
    __shared__ half s_c1[208 * PITCH];
    __shared__ half s_Yt[160 * PITCH];
    int tok = blockIdx.x;
    int tid = threadIdx.x;
    const float* xp = g_x + (size_t)tok * D_MODEL;
    float invr = g_invr[tok];
    for (int e = tid; e < 1024; e += 256)
        s_x[(e >> 5) * PITCH + (e & 31)] = __float2half_rn(xp[e] * invr * fw[e]);
    for (int e = tid; e < 160 * 32; e += 256)
        s_c2[(e >> 5) * PITCH + (e & 31)] = __float2half_rn(c2[e]);
    for (int e = tid; e < 208 * 32; e += 256){
        int v1 = e >> 5;
        s_c1[v1 * PITCH + (e & 31)] = __float2half_rn(v1 < V1N ? c1[e] : 0.f);
    }
    __syncthreads();

    int w = tid >> 5, lane = tid & 31, g = lane >> 2, tg = lane & 3;

    // stage 1: Yt[v2,i] = sum_j c2[v2,j] * xn[i,j]
    for (int id = w; id < 40; id += 8){
        int mt = id >> 2, nt = id & 3;
        float a0c = 0.f, a1c = 0.f, a2c = 0.f, a3c = 0.f;
#pragma unroll
        for (int ks = 0; ks < 2; ks++){
            int ac = ks * 16 + 2 * tg;
            uint32_t A0 = *(const uint32_t*)(s_c2 + (mt*16 + g    ) * PITCH + ac);
            uint32_t A1 = *(const uint32_t*)(s_c2 + (mt*16 + g + 8) * PITCH + ac);
            uint32_t A2 = *(const uint32_t*)(s_c2 + (mt*16 + g    ) * PITCH + ac + 8);
            uint32_t A3 = *(const uint32_t*)(s_c2 + (mt*16 + g + 8) * PITCH + ac + 8);
            uint32_t B0 = *(const uint32_t*)(s_x  + (nt*8  + g    ) * PITCH + ac);
            uint32_t B1 = *(const uint32_t*)(s_x  + (nt*8  + g    ) * PITCH + ac + 8);
            mma16816(a0c, a1c, a2c, a3c, A0, A1, A2, A3, B0, B1);
        }
        int col = nt * 8 + 2 * tg;
        *(half2*)(s_Yt + (mt*16 + g    ) * PITCH + col) = __floats2half2_rn(a0c, a1c);
        *(half2*)(s_Yt + (mt*16 + g + 8) * PITCH + col) = __floats2half2_rn(a2c, a3c);
    }
    __syncthreads();

    // stage 2: out[v1,v2] = sum_i c1[v1,i] * Yt[v2,i]
    float* op = out + (size_t)tok * (V1N * V2N);
    for (int id = w; id < 260; id += 8){
        int mt = id / 20, nt = id % 20;
        float a0c = 0.f, a1c = 0.f, a2c = 0.f, a3c = 0.f;
#pragma unroll
        for (int ks = 0; ks < 2; ks++){
            int ac = ks * 16 + 2 * tg;
            uint32_t A0 = *(const uint32_t*)(s_c1 + (mt*16 + g    ) * PITCH + ac);
            uint32_t A1 = *(const uint32_t*)(s_c1 + (mt*16 + g + 8) * PITCH + ac);
            uint32_t A2 = *(const uint32_t*)(s_c1 + (mt*16 + g    ) * PITCH + ac + 8);
            uint32_t A3 = *(const uint32_t*)(s_c1 + (mt*16 + g + 8) * PITCH + ac + 8);
            uint32_t B0 = *(const uint32_t*)(s_Yt + (nt*8  + g    ) * PITCH + ac);
            uint32_t B1 = *(const uint32_t*)(s_Yt + (nt*8  + g    ) * PITCH + ac + 8);
            mma16816(a0c, a1c, a2c, a3c, A0, A1, A2, A3, B0, B1);
        }
        int r0 = mt * 16 + g, r1 = r0 + 8, col = nt * 8 + 2 * tg;
        if (r0 < V1N) *(float2*)(op + r0 * V2N + col) = make_float2(a0c, a1c);
        if (r1 < V1N) *(float2*)(op + r1 * V2N + col) = make_float2(a2c, a3c);
    }
}

// ---------------- launch -------------------------------------------------
extern "C" void kernel_launch(void* const* d_in, const int* in_sizes, int n_in,
                              void* d_out, int out_size){
    const int*   ids = (const int*)  d_in[0];
    const float* c1  = (const float*)d_in[1];
    const float* c2  = (const float*)d_in[2];
    const float* lam = (const float*)d_in[3];
    const float* u   = (const float*)d_in[4];
    const float* v   = (const float*)d_in[5];
    const float* w1  = (const float*)d_in[6];
    const float* w2  = (const float*)d_in[7];
    const float* n1w = (const float*)d_in[8];
    const float* n2w = (const float*)d_in[9];
    const float* fw  = (const float*)d_in[10];
    float* out = (float*)d_out;

    const int smem = TC * D_MODEL * sizeof(float);   // 128 KB dynamic
    static bool attr_set = false;
    if (!attr_set){
        cudaFuncSetAttribute(k_embed, cudaFuncAttributeMaxDynamicSharedMemorySize, smem);
        cudaFuncSetAttribute(k_layer, cudaFuncAttributeMaxDynamicSharedMemorySize, smem);
        attr_set = true;
    }

    k_embed<<<BB * NC, 1024, smem>>>(ids, c1, c2, lam, v, n1w);
    for (int l = 0; l < NL; l++)
        k_layer<<<BB * NC, 1024, smem>>>(lam, u, v, w1, w2, n1w, n2w, l);
    k_logits<<<NTOK, 256>>>(c1, c2, fw, out);
}

// round 4
// speedup vs baseline: 1.6586x; 1.0955x over previous
#include <cuda_runtime.h>
#include <cuda_fp16.h>
#include <cstdint>

#define D_MODEL 1024
#define BB 2
#define SS 2048
#define NTOK (BB*SS)
#define V1N 200
#define V2N 160
#define NL 8
#define TC 32
#define NC (SS/TC)     /* 64 */
#define NBLK (BB*NC)   /* 128 */
#define EPS 1e-6f

// ---------------- scratch -------------------------------------------------
__device__ float g_x[NTOK * D_MODEL];          // final x (for logits)
__device__ float g_invr[NTOK];                 // final rmsnorm scale
__device__ float g_hfin[2][NBLK * D_MODEL];    // chunk-local scan results (ping-pong)
__device__ unsigned g_barcnt[NL];              // monotone grid-barrier counters

// ---------------- helpers -------------------------------------------------
__device__ __forceinline__ float warp_sum(float v){
#pragma unroll
    for (int o = 16; o; o >>= 1) v += __shfl_xor_sync(0xffffffffu, v, o);
    return v;
}
__device__ __forceinline__ float sigmoidf_(float x){ return 1.f / (1.f + expf(-x)); }
__device__ __forceinline__ float geluf_(float x){
    float x3 = x * x * x;
    return 0.5f * x * (1.f + tanhf(0.7978845608028654f * (x + 0.044715f * x3)));
}
__device__ __forceinline__ void mma16816(float& d0, float& d1, float& d2, float& d3,
                                         uint32_t a0, uint32_t a1, uint32_t a2, uint32_t a3,
                                         uint32_t b0, uint32_t b1){
    asm volatile(
        "mma.sync.aligned.m16n8k16.row.col.f32.f16.f16.f32 "
        "{%0,%1,%2,%3},{%4,%5,%6,%7},{%8,%9},{%0,%1,%2,%3};\n"
        : "+f"(d0), "+f"(d1), "+f"(d2), "+f"(d3)
        : "r"(a0), "r"(a1), "r"(a2), "r"(a3), "r"(b0), "r"(b1));
}

// grid-wide barrier: monotone counter, no resets (replay-safe).
// Producer side published data + __threadfence before arriving; consumers read
// cross-block data with __ldcg (L2 is the coherence point).
__device__ __forceinline__ void grid_bar(int i){
    __syncthreads();
    if (threadIdx.x == 0){
        __threadfence();
        unsigned my = atomicAdd(&g_barcnt[i], 1u);
        unsigned target = (my | (unsigned)(NBLK - 1)) + 1u;   // next multiple of NBLK
        while (*(volatile unsigned*)&g_barcnt[i] < target) {}
    }
    __syncthreads();
}

// =========================================================================
// persistent model kernel: embed + 8 fused layers. x stays in smem.
// block = one chunk (32 tokens x 1024 channels), grid = 128 (one wave).
// =========================================================================
__global__ __launch_bounds__(1024, 1) void k_model(
    const int* __restrict__ ids, const float* __restrict__ c1,
    const float* __restrict__ c2, const float* __restrict__ lam,
    const float* __restrict__ uu, const float* __restrict__ vv,
    const float* __restrict__ w1, const float* __restrict__ w2,
    const float* __restrict__ n1w, const float* __restrict__ n2w)
{
    extern __shared__ float sx[];              // TC * D_MODEL = 128 KB
    __shared__ float s_n2w[D_MODEL], s_w1x[D_MODEL], s_w1y[D_MODEL];
    __shared__ float s_w2a[D_MODEL], s_w2b[D_MODEL];
    __shared__ float s_ir[TC];

    int b  = blockIdx.x >> 6;
    int ch = blockIdx.x & (NC - 1);
    int c  = threadIdx.x;
    int t  = c >> 5, lane = c & 31;
    int tok0 = b * SS + ch * TC;

    // ---- embed (warp = token) into smem ----
    {
        int id = ids[tok0 + t];
        const float* r1 = c1 + (id / V2N) * 32;
        const float* r2 = c2 + (id % V2N) * 32;
        float* xr = sx + t * D_MODEL;
        float ss = 0.f;
#pragma unroll
        for (int k = 0; k < 8; k++){
            int e = k * 128 + lane * 4;
            float a = r1[e >> 5];
            float4 bq = *(const float4*)(r2 + (e & 31));
            float4 v4; v4.x = a*bq.x; v4.y = a*bq.y; v4.z = a*bq.z; v4.w = a*bq.w;
            *(float4*)(xr + e) = v4;
            ss += v4.x*v4.x + v4.y*v4.y + v4.z*v4.z + v4.w*v4.w;
        }
        ss = warp_sum(ss);
        if (lane == 0) s_ir[t] = rsqrtf(ss * (1.f/1024.f) + EPS);
    }
    __syncthreads();

    // ---- phase A for layer 0 (channel layout) ----
    {
        float a0  = sigmoidf_(lam[c]);
        float vn0 = vv[c] * n1w[c];
        float h = 0.f;
#pragma unroll
        for (int tt = 0; tt < TC; tt++)
            h = fmaf(a0, h, (vn0 * s_ir[tt]) * sx[tt * D_MODEL + c]);
        g_hfin[0][blockIdx.x * D_MODEL + c] = h;
    }

    for (int l = 0; l < NL; l++){
        grid_bar(l);   // hfin for this layer is now published by all blocks

        // stage per-layer params (independent loads; overlap carry latency)
        float w_n2 = n2w[l * D_MODEL + c];
        float2 w1p = ((const float2*)(w1 + (size_t)l * D_MODEL * 2))[c];
        float w2av = w2[(size_t)l * 2 * D_MODEL + c];
        float w2bv = w2[(size_t)l * 2 * D_MODEL + D_MODEL + c];

        int off = l * D_MODEL + c;
        float a  = sigmoidf_(lam[off]);
        float vn = vv[off] * n1w[off];
        float un = uu[off];
        float aT = a * a; aT *= aT; aT *= aT; aT *= aT; aT *= aT;   // a^32

        // cross-chunk carry: Horner over earlier chunks' hfin (L2, __ldcg)
        const float* hf = g_hfin[l & 1] + (size_t)b * NC * D_MODEL + c;
        float carry = 0.f;
#pragma unroll 16
        for (int k = 0; k < ch; k++)
            carry = fmaf(aT, carry, __ldcg(hf + (size_t)k * D_MODEL));

        s_n2w[c] = w_n2; s_w1x[c] = w1p.x; s_w1y[c] = w1p.y;
        s_w2a[c] = w2av; s_w2b[c] = w2bv;

        // scan + residual (channel layout, smem RMW)
        float h = carry;
#pragma unroll
        for (int tt = 0; tt < TC; tt++){
            float xv = sx[tt * D_MODEL + c];
            h = fmaf(a, h, (vn * s_ir[tt]) * xv);
            sx[tt * D_MODEL + c] = fmaf(un, h, xv);
        }
        __syncthreads();

        // FFN (warp = token), x held in registers
        float* xr = sx + t * D_MODEL;
        float xv[32];
        float ss = 0.f;
#pragma unroll
        for (int k = 0; k < 8; k++){
            float4 q = *(const float4*)(xr + k * 128 + lane * 4);
            xv[4*k]=q.x; xv[4*k+1]=q.y; xv[4*k+2]=q.z; xv[4*k+3]=q.w;
            ss += q.x*q.x + q.y*q.y + q.z*q.z + q.w*q.w;
        }
        ss = warp_sum(ss);
        float invr = rsqrtf(ss * (1.f/1024.f) + EPS);

        float d0 = 0.f, d1 = 0.f;
#pragma unroll
        for (int k = 0; k < 8; k++){
            int e = k * 128 + lane * 4;
            float4 nw = *(const float4*)(s_n2w + e);
            float4 wx = *(const float4*)(s_w1x + e);
            float4 wy = *(const float4*)(s_w1y + e);
#pragma unroll
            for (int r = 0; r < 4; r++){
                float hh = xv[4*k+r] * invr * ((const float*)&nw)[r];
                d0 = fmaf(hh, ((const float*)&wx)[r], d0);
                d1 = fmaf(hh, ((const float*)&wy)[r], d1);
            }
        }
        d0 = warp_sum(d0);
        d1 = warp_sum(d1);
        float g0 = geluf_(d0), g1 = geluf_(d1);

        float ss2 = 0.f;
        float* xg = g_x + (size_t)(tok0 + t) * D_MODEL;
#pragma unroll
        for (int k = 0; k < 8; k++){
            int e = k * 128 + lane * 4;
            float4 wa = *(const float4*)(s_w2a + e);
            float4 wb = *(const float4*)(s_w2b + e);
            float4 o;
            o.x = xv[4*k+0] + g0*wa.x + g1*wb.x;
            o.y = xv[4*k+1] + g0*wa.y + g1*wb.y;
            o.z = xv[4*k+2] + g0*wa.z + g1*wb.z;
            o.w = xv[4*k+3] + g0*wa.w + g1*wb.w;
            if (l < NL - 1) *(float4*)(xr + e) = o;   // keep in smem
            else            *(float4*)(xg + e) = o;   // final: to global for logits
            ss2 += o.x*o.x + o.y*o.y + o.z*o.z + o.w*o.w;
        }
        ss2 = warp_sum(ss2);
        if (lane == 0){
            float r2 = rsqrtf(ss2 * (1.f/1024.f) + EPS);
            s_ir[t] = r2;                      // safe: old s_ir last read before prev sync
            if (l == NL - 1) g_invr[tok0 + t] = r2;
        }
        __syncthreads();

        // phase A for next layer (channel layout)
        if (l < NL - 1){
            int off2 = (l + 1) * D_MODEL + c;
            float a2  = sigmoidf_(lam[off2]);
            float vn2 = vv[off2] * n1w[off2];
            float h2 = 0.f;
#pragma unroll
            for (int tt = 0; tt < TC; tt++)
                h2 = fmaf(a2, h2, (vn2 * s_ir[tt]) * sx[tt * D_MODEL + c]);
            g_hfin[(l + 1) & 1][blockIdx.x * D_MODEL + c] = h2;
        }
    }
}

// =========================================================================
// logits: TT-factored, fp16 HMMA, one token per CTA (DRAM-store-bound)
// =========================================================================
#define PITCH 40
__global__ __launch_bounds__(256) void k_logits(const float* __restrict__ c1,
                                                const float* __restrict__ c2,
                                                const float* __restrict__ fw,
                                                float* __restrict__ out){
    __shared__ half s_x [32  * PITCH];
    __shared__ half s_c2[160 * PITCH];
    __shared__ half s_c1[208 * PITCH];
    __shared__ half s_Yt[160 * PITCH];
    int tok = blockIdx.x;
    int tid = threadIdx.x;
    const float* xp = g_x + (size_t)tok * D_MODEL;
    float invr = g_invr[tok];
    for (int e = tid; e < 1024; e += 256)
        s_x[(e >> 5) * PITCH + (e & 31)] = __float2half_rn(xp[e] * invr * fw[e]);
    for (int e = tid; e < 160 * 32; e += 256)
        s_c2[(e >> 5) * PITCH + (e & 31)] = __float2half_rn(c2[e]);
    for (int e = tid; e < 208 * 32; e += 256){
        int v1 = e >> 5;
        s_c1[v1 * PITCH + (e & 31)] = __float2half_rn(v1 < V1N ? c1[e] : 0.f);
    }
    __syncthreads();

    int w = tid >> 5, lane = tid & 31, g = lane >> 2, tg = lane & 3;

    // stage 1: Yt[v2,i] = sum_j c2[v2,j] * xn[i,j]
    for (int id = w; id < 40; id += 8){
        int mt = id >> 2, nt = id & 3;
        float a0c = 0.f, a1c = 0.f, a2c = 0.f, a3c = 0.f;
#pragma unroll
        for (int ks = 0; ks < 2; ks++){
            int ac = ks * 16 + 2 * tg;
            uint32_t A0 = *(const uint32_t*)(s_c2 + (mt*16 + g    ) * PITCH + ac);
            uint32_t A1 = *(const uint32_t*)(s_c2 + (mt*16 + g + 8) * PITCH + ac);
            uint32_t A2 = *(const uint32_t*)(s_c2 + (mt*16 + g    ) * PITCH + ac + 8);
            uint32_t A3 = *(const uint32_t*)(s_c2 + (mt*16 + g + 8) * PITCH + ac + 8);
            uint32_t B0 = *(const uint32_t*)(s_x  + (nt*8  + g    ) * PITCH + ac);
            uint32_t B1 = *(const uint32_t*)(s_x  + (nt*8  + g    ) * PITCH + ac + 8);
            mma16816(a0c, a1c, a2c, a3c, A0, A1, A2, A3, B0, B1);
        }
        int col = nt * 8 + 2 * tg;
        *(half2*)(s_Yt + (mt*16 + g    ) * PITCH + col) = __floats2half2_rn(a0c, a1c);
        *(half2*)(s_Yt + (mt*16 + g + 8) * PITCH + col) = __floats2half2_rn(a2c, a3c);
    }
    __syncthreads();

    // stage 2: out[v1,v2] = sum_i c1[v1,i] * Yt[v2,i]
    float* op = out + (size_t)tok * (V1N * V2N);
    for (int id = w; id < 260; id += 8){
        int mt = id / 20, nt = id % 20;
        float a0c = 0.f, a1c = 0.f, a2c = 0.f, a3c = 0.f;
#pragma unroll
        for (int ks = 0; ks < 2; ks++){
            int ac = ks * 16 + 2 * tg;
            uint32_t A0 = *(const uint32_t*)(s_c1 + (mt*16 + g    ) * PITCH + ac);
            uint32_t A1 = *(const uint32_t*)(s_c1 + (mt*16 + g + 8) * PITCH + ac);
            uint32_t A2 = *(const uint32_t*)(s_c1 + (mt*16 + g    ) * PITCH + ac + 8);
            uint32_t A3 = *(const uint32_t*)(s_c1 + (mt*16 + g + 8) * PITCH + ac + 8);
            uint32_t B0 = *(const uint32_t*)(s_Yt + (nt*8  + g    ) * PITCH + ac);
            uint32_t B1 = *(const uint32_t*)(s_Yt + (nt*8  + g    ) * PITCH + ac + 8);
            mma16816(a0c, a1c, a2c, a3c, A0, A1, A2, A3, B0, B1);
        }
        int r0 = mt * 16 + g, r1 = r0 + 8, col = nt * 8 + 2 * tg;
        if (r0 < V1N) *(float2*)(op + r0 * V2N + col) = make_float2(a0c, a1c);
        if (r1 < V1N) *(float2*)(op + r1 * V2N + col) = make_float2(a2c, a3c);
    }
}

// ---------------- launch --------------------------------------------------
extern "C" void kernel_launch(void* const* d_in, const int* in_sizes, int n_in,
                              void* d_out, int out_size){
    const int*   ids = (const int*)  d_in[0];
    const float* c1  = (const float*)d_in[1];
    const float* c2  = (const float*)d_in[2];
    const float* lam = (const float*)d_in[3];
    const float* u   = (const float*)d_in[4];
    const float* v   = (const float*)d_in[5];
    const float* w1  = (const float*)d_in[6];
    const float* w2  = (const float*)d_in[7];
    const float* n1w = (const float*)d_in[8];
    const float* n2w = (const float*)d_in[9];
    const float* fw  = (const float*)d_in[10];
    float* out = (float*)d_out;

    const int smem = TC * D_MODEL * sizeof(float);   // 128 KB dynamic
    static bool attr_set = false;
    if (!attr_set){
        cudaFuncSetAttribute(k_model, cudaFuncAttributeMaxDynamicSharedMemorySize, smem);
        attr_set = true;
    }

    k_model<<<NBLK, 1024, smem>>>(ids, c1, c2, lam, u, v, w1, w2, n1w, n2w);
    k_logits<<<NTOK, 256>>>(c1, c2, fw, out);
}

// round 6
// speedup vs baseline: 1.9323x; 1.1650x over previous
#include <cuda_runtime.h>
#include <cuda_fp16.h>
#include <cstdint>

#define D_MODEL 1024
#define BB 2
#define SS 2048
#define NTOK (BB*SS)
#define V1N 200
#define V2N 160
#define NL 8
#define TC 32
#define NC (SS/TC)     /* 64 */
#define NBLK (BB*NC)   /* 128 */
#define EPS 1e-6f

// ---------------- scratch -------------------------------------------------
__device__ float g_x[NTOK * D_MODEL];          // final x (for logits)
__device__ float g_invr[NTOK];                 // final rmsnorm scale
__device__ float g_hfin[2][NBLK * D_MODEL];    // chunk-local scan results (ping-pong)
__device__ unsigned g_barcnt[NL];              // monotone grid-barrier counters
__device__ uint32_t g_c1h[13 * 256];           // c1 fp16 frags: [mt][lane][ks][j]
__device__ uint32_t g_c2h[10 * 256];           // c2 fp16 frags: [mt][lane][ks][j]

// ---------------- helpers -------------------------------------------------
__device__ __forceinline__ float warp_sum(float v){
#pragma unroll
    for (int o = 16; o; o >>= 1) v += __shfl_xor_sync(0xffffffffu, v, o);
    return v;
}
__device__ __forceinline__ float sigmoidf_(float x){ return 1.f / (1.f + expf(-x)); }
__device__ __forceinline__ float geluf_(float x){
    float x3 = x * x * x;
    return 0.5f * x * (1.f + tanhf(0.7978845608028654f * (x + 0.044715f * x3)));
}
__device__ __forceinline__ void mma16816(float& d0, float& d1, float& d2, float& d3,
                                         uint32_t a0, uint32_t a1, uint32_t a2, uint32_t a3,
                                         uint32_t b0, uint32_t b1){
    asm volatile(
        "mma.sync.aligned.m16n8k16.row.col.f32.f16.f16.f32 "
        "{%0,%1,%2,%3},{%4,%5,%6,%7},{%8,%9},{%0,%1,%2,%3};\n"
        : "+f"(d0), "+f"(d1), "+f"(d2), "+f"(d3)
        : "r"(a0), "r"(a1), "r"(a2), "r"(a3), "r"(b0), "r"(b1));
}

__device__ __forceinline__ void grid_bar(int i){
    __syncthreads();
    if (threadIdx.x == 0){
        __threadfence();
        unsigned my = atomicAdd(&g_barcnt[i], 1u);
        unsigned target = (my | (unsigned)(NBLK - 1)) + 1u;
        while (*(volatile unsigned*)&g_barcnt[i] < target) {}
    }
    __syncthreads();
}

// =========================================================================
// prep: pack c1/c2 into fp16 MMA A-fragment layout (row-major m16k16 frags)
// frag j: row = g + (j&1)*8, col = ks*16 + 2*tg + (j>>1)*8
// =========================================================================
__global__ void k_prep(const float* __restrict__ c1, const float* __restrict__ c2){
    int tid = blockIdx.x * blockDim.x + threadIdx.x;
    const int T1 = 13 * 256, T2 = 10 * 256;
    for (int idx = tid; idx < T1 + T2; idx += gridDim.x * blockDim.x){
        bool is1 = idx < T1;
        int rem  = is1 ? idx : idx - T1;
        int j = rem & 3, ks = (rem >> 2) & 1, lane = (rem >> 3) & 31, mt = rem >> 8;
        int g = lane >> 2, tg = lane & 3;
        int row = mt * 16 + g + (j & 1) * 8;
        int col = ks * 16 + 2 * tg + ((j >> 1) & 1) * 8;
        if (is1){
            uint32_t val = 0;
            if (row < V1N){
                half2 h = __floats2half2_rn(c1[row * 32 + col], c1[row * 32 + col + 1]);
                val = *(uint32_t*)&h;
            }
            g_c1h[rem] = val;
        } else {
            half2 h = __floats2half2_rn(c2[row * 32 + col], c2[row * 32 + col + 1]);
            g_c2h[rem] = *(uint32_t*)&h;
        }
    }
}

// =========================================================================
// persistent model kernel: embed + 8 fused layers. x stays in smem.
// =========================================================================
__global__ __launch_bounds__(1024, 1) void k_model(
    const int* __restrict__ ids, const float* __restrict__ c1,
    const float* __restrict__ c2, const float* __restrict__ lam,
    const float* __restrict__ uu, const float* __restrict__ vv,
    const float* __restrict__ w1, const float* __restrict__ w2,
    const float* __restrict__ n1w, const float* __restrict__ n2w)
{
    extern __shared__ float sx[];              // TC * D_MODEL = 128 KB
    __shared__ float s_n2w[D_MODEL], s_w1x[D_MODEL], s_w1y[D_MODEL];
    __shared__ float s_w2a[D_MODEL], s_w2b[D_MODEL];
    __shared__ float s_ir[TC];

    int b  = blockIdx.x >> 6;
    int ch = blockIdx.x & (NC - 1);
    int c  = threadIdx.x;
    int t  = c >> 5, lane = c & 31;
    int tok0 = b * SS + ch * TC;

    // ---- embed (warp = token) into smem ----
    {
        int id = ids[tok0 + t];
        const float* r1 = c1 + (id / V2N) * 32;
        const float* r2 = c2 + (id % V2N) * 32;
        float* xr = sx + t * D_MODEL;
        float ss = 0.f;
#pragma unroll
        for (int k = 0; k < 8; k++){
            int e = k * 128 + lane * 4;
            float a = r1[e >> 5];
            float4 bq = *(const float4*)(r2 + (e & 31));
            float4 v4; v4.x = a*bq.x; v4.y = a*bq.y; v4.z = a*bq.z; v4.w = a*bq.w;
            *(float4*)(xr + e) = v4;
            ss += v4.x*v4.x + v4.y*v4.y + v4.z*v4.z + v4.w*v4.w;
        }
        ss = warp_sum(ss);
        if (lane == 0) s_ir[t] = rsqrtf(ss * (1.f/1024.f) + EPS);
    }
    __syncthreads();

    // ---- phase A for layer 0 ----
    {
        float a0  = sigmoidf_(lam[c]);
        float vn0 = vv[c] * n1w[c];
        float h = 0.f;
#pragma unroll
        for (int tt = 0; tt < TC; tt++)
            h = fmaf(a0, h, (vn0 * s_ir[tt]) * sx[tt * D_MODEL + c]);
        g_hfin[0][blockIdx.x * D_MODEL + c] = h;
    }

    for (int l = 0; l < NL; l++){
        grid_bar(l);

        float w_n2 = n2w[l * D_MODEL + c];
        float2 w1p = ((const float2*)(w1 + (size_t)l * D_MODEL * 2))[c];
        float w2av = w2[(size_t)l * 2 * D_MODEL + c];
        float w2bv = w2[(size_t)l * 2 * D_MODEL + D_MODEL + c];

        int off = l * D_MODEL + c;
        float a  = sigmoidf_(lam[off]);
        float vn = vv[off] * n1w[off];
        float un = uu[off];
        float aT = a * a; aT *= aT; aT *= aT; aT *= aT; aT *= aT;   // a^32

        const float* hf = g_hfin[l & 1] + (size_t)b * NC * D_MODEL + c;
        float carry = 0.f;
#pragma unroll 16
        for (int k = 0; k < ch; k++)
            carry = fmaf(aT, carry, __ldcg(hf + (size_t)k * D_MODEL));

        s_n2w[c] = w_n2; s_w1x[c] = w1p.x; s_w1y[c] = w1p.y;
        s_w2a[c] = w2av; s_w2b[c] = w2bv;

        float h = carry;
#pragma unroll
        for (int tt = 0; tt < TC; tt++){
            float xv = sx[tt * D_MODEL + c];
            h = fmaf(a, h, (vn * s_ir[tt]) * xv);
            sx[tt * D_MODEL + c] = fmaf(un, h, xv);
        }
        __syncthreads();

        float* xr = sx + t * D_MODEL;
        float xv[32];
        float ss = 0.f;
#pragma unroll
        for (int k = 0; k < 8; k++){
            float4 q = *(const float4*)(xr + k * 128 + lane * 4);
            xv[4*k]=q.x; xv[4*k+1]=q.y; xv[4*k+2]=q.z; xv[4*k+3]=q.w;
            ss += q.x*q.x + q.y*q.y + q.z*q.z + q.w*q.w;
        }
        ss = warp_sum(ss);
        float invr = rsqrtf(ss * (1.f/1024.f) + EPS);

        float d0 = 0.f, d1 = 0.f;
#pragma unroll
        for (int k = 0; k < 8; k++){
            int e = k * 128 + lane * 4;
            float4 nw = *(const float4*)(s_n2w + e);
            float4 wx = *(const float4*)(s_w1x + e);
            float4 wy = *(const float4*)(s_w1y + e);
#pragma unroll
            for (int r = 0; r < 4; r++){
                float hh = xv[4*k+r] * invr * ((const float*)&nw)[r];
                d0 = fmaf(hh, ((const float*)&wx)[r], d0);
                d1 = fmaf(hh, ((const float*)&wy)[r], d1);
            }
        }
        d0 = warp_sum(d0);
        d1 = warp_sum(d1);
        float g0 = geluf_(d0), g1 = geluf_(d1);

        float ss2 = 0.f;
        float* xg = g_x + (size_t)(tok0 + t) * D_MODEL;
#pragma unroll
        for (int k = 0; k < 8; k++){
            int e = k * 128 + lane * 4;
            float4 wa = *(const float4*)(s_w2a + e);
            float4 wb = *(const float4*)(s_w2b + e);
            float4 o;
            o.x = xv[4*k+0] + g0*wa.x + g1*wb.x;
            o.y = xv[4*k+1] + g0*wa.y + g1*wb.y;
            o.z = xv[4*k+2] + g0*wa.z + g1*wb.z;
            o.w = xv[4*k+3] + g0*wa.w + g1*wb.w;
            if (l < NL - 1) *(float4*)(xr + e) = o;
            else            *(float4*)(xg + e) = o;
            ss2 += o.x*o.x + o.y*o.y + o.z*o.z + o.w*o.w;
        }
        ss2 = warp_sum(ss2);
        if (lane == 0){
            float r2 = rsqrtf(ss2 * (1.f/1024.f) + EPS);
            s_ir[t] = r2;
            if (l == NL - 1) g_invr[tok0 + t] = r2;
        }
        __syncthreads();

        if (l < NL - 1){
            int off2 = (l + 1) * D_MODEL + c;
            float a2  = sigmoidf_(lam[off2]);
            float vn2 = vv[off2] * n1w[off2];
            float h2 = 0.f;
#pragma unroll
            for (int tt = 0; tt < TC; tt++)
                h2 = fmaf(a2, h2, (vn2 * s_ir[tt]) * sx[tt * D_MODEL + c]);
            g_hfin[(l + 1) & 1][blockIdx.x * D_MODEL + c] = h2;
        }
    }
}

// =========================================================================
// logits: TT-factored fp16 MMA. A-fragments from prepacked global tables
// (register-cached per mt-row); only B-fragments come from smem.
// =========================================================================
#define PITCH 40
__global__ __launch_bounds__(256) void k_logits(const float* __restrict__ fw,
                                                float* __restrict__ out){
    __shared__ half s_x [32  * PITCH];   // normalized token, fp16
    __shared__ half s_Yt[160 * PITCH];   // stage-1 result, fp16
    int tok = blockIdx.x;
    int tid = threadIdx.x;

    // fill s_x: x * invr * fw -> fp16
    {
        const float* xp = g_x + (size_t)tok * D_MODEL;
        float invr = g_invr[tok];
        int e = tid * 4;                              // 4 elems, same row
        int row = e >> 5, col = e & 31;
        float4 q = *(const float4*)(xp + e);
        float4 f = *(const float4*)(fw + e);
        half* dst = s_x + row * PITCH + col;
        *(half2*)(dst    ) = __floats2half2_rn(q.x * invr * f.x, q.y * invr * f.y);
        *(half2*)(dst + 2) = __floats2half2_rn(q.z * invr * f.z, q.w * invr * f.w);
    }
    __syncthreads();

    int w = tid >> 5, lane = tid & 31, g = lane >> 2, tg = lane & 3;
    const uint4* c2f = (const uint4*)g_c2h;   // [mt][lane][ks] -> uint4 (4 frags)
    const uint4* c1f = (const uint4*)g_c1h;

    // ---- stage 1: Yt[v2,i] = sum_j c2[v2,j]*xn[i,j]; 10 mt x 4 nt tiles ----
    for (int id = w; id < 40; id += 8){
        int mt = id >> 2, nt = id & 3;
        uint4 qa0 = c2f[(mt * 32 + lane) * 2 + 0];
        uint4 qa1 = c2f[(mt * 32 + lane) * 2 + 1];
        float a0c = 0.f, a1c = 0.f, a2c = 0.f, a3c = 0.f;
        {
            int ac = 2 * tg;
            uint32_t B0 = *(const uint32_t*)(s_x + (nt*8 + g) * PITCH + ac);
            uint32_t B1 = *(const uint32_t*)(s_x + (nt*8 + g) * PITCH + ac + 8);
            mma16816(a0c, a1c, a2c, a3c, qa0.x, qa0.y, qa0.z, qa0.w, B0, B1);
            B0 = *(const uint32_t*)(s_x + (nt*8 + g) * PITCH + ac + 16);
            B1 = *(const uint32_t*)(s_x + (nt*8 + g) * PITCH + ac + 24);
            mma16816(a0c, a1c, a2c, a3c, qa1.x, qa1.y, qa1.z, qa1.w, B0, B1);
        }
        int col = nt * 8 + 2 * tg;
        *(half2*)(s_Yt + (mt*16 + g    ) * PITCH + col) = __floats2half2_rn(a0c, a1c);
        *(half2*)(s_Yt + (mt*16 + g + 8) * PITCH + col) = __floats2half2_rn(a2c, a3c);
    }
    __syncthreads();

    // ---- stage 2: out[v1,v2] = sum_i c1[v1,i]*Yt[v2,i]; 13 mt x 20 nt ----
    // contiguous per-warp tile ranges so A-frags reload only on mt change
    float* op = out + (size_t)tok * (V1N * V2N);
    int start = (w * 260) >> 3;
    int end   = ((w + 1) * 260) >> 3;
    int mt = start / 20, nt = start - mt * 20;
    uint4 qa0 = c1f[(mt * 32 + lane) * 2 + 0];
    uint4 qa1 = c1f[(mt * 32 + lane) * 2 + 1];
    for (int id = start; id < end; id++){
        float a0c = 0.f, a1c = 0.f, a2c = 0.f, a3c = 0.f;
        {
            int ac = 2 * tg;
            const half* yb = s_Yt + (nt*8 + g) * PITCH;
            uint32_t B0 = *(const uint32_t*)(yb + ac);
            uint32_t B1 = *(const uint32_t*)(yb + ac + 8);
            mma16816(a0c, a1c, a2c, a3c, qa0.x, qa0.y, qa0.z, qa0.w, B0, B1);
            B0 = *(const uint32_t*)(yb + ac + 16);
            B1 = *(const uint32_t*)(yb + ac + 24);
            mma16816(a0c, a1c, a2c, a3c, qa1.x, qa1.y, qa1.z, qa1.w, B0, B1);
        }
        int r0 = mt * 16 + g, col = nt * 8 + 2 * tg;
        *(float2*)(op + r0 * V2N + col) = make_float2(a0c, a1c);      // r0<200 always
        if (r0 + 8 < V1N)
            *(float2*)(op + (r0 + 8) * V2N + col) = make_float2(a2c, a3c);
        if (++nt == 20){
            nt = 0; mt++;
            if (id + 1 < end){
                qa0 = c1f[(mt * 32 + lane) * 2 + 0];
                qa1 = c1f[(mt * 32 + lane) * 2 + 1];
            }
        }
    }
}

// ---------------- launch --------------------------------------------------
extern "C" void kernel_launch(void* const* d_in, const int* in_sizes, int n_in,
                              void* d_out, int out_size){
    const int*   ids = (const int*)  d_in[0];
    const float* c1  = (const float*)d_in[1];
    const float* c2  = (const float*)d_in[2];
    const float* lam = (const float*)d_in[3];
    const float* u   = (const float*)d_in[4];
    const float* v   = (const float*)d_in[5];
    const float* w1  = (const float*)d_in[6];
    const float* w2  = (const float*)d_in[7];
    const float* n1w = (const float*)d_in[8];
    const float* n2w = (const float*)d_in[9];
    const float* fw  = (const float*)d_in[10];
    float* out = (float*)d_out;

    const int smem = TC * D_MODEL * sizeof(float);   // 128 KB dynamic
    static bool attr_set = false;
    if (!attr_set){
        cudaFuncSetAttribute(k_model, cudaFuncAttributeMaxDynamicSharedMemorySize, smem);
        attr_set = true;
    }

    k_prep<<<8, 256>>>(c1, c2);
    k_model<<<NBLK, 1024, smem>>>(ids, c1, c2, lam, u, v, w1, w2, n1w, n2w);
    k_logits<<<NTOK, 256>>>(fw, out);
}